// round 16
// baseline (speedup 1.0000x reference)
#include <cuda_runtime.h>
#include <cuda_bf16.h>

// img : (1, 64, 64, 1024) float32, NHWC
// rois: (1, 512, 4) int32  -> (x, y, w, h)
// out : (1, 512, 7, 7, 1024) float32
#define POOL   7
#define NROIS  512
#define IMG_W  64

typedef unsigned long long u64t;

// One pixel = 1024 floats = 4096 bytes = 128 lanes of 32 bytes.
struct Px8 { u64t v[4]; };   // 32 bytes = 4 packed f32x2

// ---- packed f32x2 helpers (sm_103a) ----
__device__ __forceinline__ u64t pk(float v) {
    u64t r;
    asm("mov.b64 %0, {%1, %1};" : "=l"(r) : "f"(v));
    return r;
}
__device__ __forceinline__ u64t mul2(u64t a, u64t b) {
    u64t r;
    asm("mul.rn.f32x2 %0, %1, %2;" : "=l"(r) : "l"(a), "l"(b));
    return r;
}
__device__ __forceinline__ u64t fma2(u64t a, u64t b, u64t c) {
    u64t r;
    asm("fma.rn.f32x2 %0, %1, %2, %3;" : "=l"(r) : "l"(a), "l"(b), "l"(c));
    return r;
}

// 256-bit global load (sm_100+): one instruction, 32 bytes, non-coherent path.
__device__ __forceinline__ Px8 ldg256(const char* p) {
    Px8 r;
    asm("ld.global.nc.v4.b64 {%0, %1, %2, %3}, [%4];"
        : "=l"(r.v[0]), "=l"(r.v[1]), "=l"(r.v[2]), "=l"(r.v[3]) : "l"(p));
    return r;
}
// 256-bit streaming store (output never re-read).
__device__ __forceinline__ void stg256(char* p, Px8 x) {
    asm volatile("st.global.cs.v4.b64 [%0], {%1, %2, %3, %4};"
                 :: "l"(p), "l"(x.v[0]), "l"(x.v[1]), "l"(x.v[2]), "l"(x.v[3])
                 : "memory");
}

__device__ __forceinline__ Px8 blend8(const Px8& v00, const Px8& v01,
                                      const Px8& v10, const Px8& v11,
                                      float fx, float fy) {
    const float w11 = fx * fy;
    const float w01 = fx - w11;          // fx*(1-fy)
    const float w10 = fy - w11;          // (1-fx)*fy
    const float w00 = 1.0f - fx - w10;   // (1-fx)*(1-fy)
    const u64t W00 = pk(w00), W01 = pk(w01), W10 = pk(w10), W11 = pk(w11);
    Px8 o;
    #pragma unroll
    for (int i = 0; i < 4; ++i)
        o.v[i] = fma2(v11.v[i], W11,
                 fma2(v10.v[i], W10,
                 fma2(v01.v[i], W01, mul2(v00.v[i], W00))));
    return o;
}

// One CTA per (roi, py) output row: 7 px cells, 128 threads, one 32B lane
// each. 256-bit LDG/STG halve the memory-instruction count (and L1tex queue
// entries) per byte vs the 128-bit version; per-thread in-flight bytes double
// so no explicit software pipeline is needed. Warp-uniform horizontal reuse:
// when x0(px+1) == x1(px), the left column comes from registers.
__global__ __launch_bounds__(128)
void roi_pool_kernel(const float* __restrict__ img,
                     const int*   __restrict__ rois,
                     float*       __restrict__ out)
{
    const int bid = blockIdx.x;           // roi*7 + py
    const int roi = bid / POOL;
    const int py  = bid - roi * POOL;

    const int4 r = __ldg(((const int4*)rois) + roi);   // x, y, w, h

    // Loop-invariant y-axis work (match reference fp32 arithmetic exactly)
    const float stepx = (float)r.z / (float)POOL;
    const float sy = (float)py * ((float)r.w / (float)POOL);
    const int   y0 = (int)sy;
    const float fy = sy - (float)y0;
    const int   y1 = min(y0 + 1, r.w - 1);
    const int   wm1 = r.z - 1;

    const int c = threadIdx.x;            // 0..127: 32B lane within pixel
    const char* ib = (const char*)img;
    // Row bases in bytes (pixel stride 4096B), including x-origin and lane.
    const unsigned row0 = (unsigned)((r.y + y0) * IMG_W + r.x) * 4096u + (unsigned)c * 32u;
    const unsigned row1 = (unsigned)((r.y + y1) * IMG_W + r.x) * 4096u + (unsigned)c * 32u;

    char* optr = (char*)out + (size_t)bid * (POOL * 4096) + (unsigned)c * 32u;

    // ---- px = 0 (sx = 0, x0 = 0, fx = 0) ----
    float fxc = 0.0f;
    unsigned prev_x1 = (unsigned)min(1, wm1);
    Px8 a00 = ldg256(ib + row0);
    Px8 a10 = ldg256(ib + row1);
    Px8 a01 = ldg256(ib + row0 + prev_x1 * 4096u);
    Px8 a11 = ldg256(ib + row1 + prev_x1 * 4096u);

    #pragma unroll
    for (int px = 0; px < POOL; ++px) {
        stg256(optr, blend8(a00, a01, a10, a11, fxc, fy));
        optr += 4096;

        if (px + 1 < POOL) {
            const float sx = (float)(px + 1) * stepx;
            const int   x0 = (int)sx;
            fxc = sx - (float)x0;
            const unsigned x1n = (unsigned)min(x0 + 1, wm1);
            const bool reuse = ((unsigned)x0 == prev_x1);   // warp-uniform
            const unsigned u0 = (unsigned)x0 * 4096u;
            const unsigned u1 = x1n * 4096u;
            prev_x1 = x1n;

            // Right column always loaded; left column often from registers.
            const Px8 n01 = ldg256(ib + row0 + u1);
            const Px8 n11 = ldg256(ib + row1 + u1);
            if (reuse) { a00 = a01; a10 = a11; }
            else       { a00 = ldg256(ib + row0 + u0);
                         a10 = ldg256(ib + row1 + u0); }
            a01 = n01; a11 = n11;
        }
    }
}

extern "C" void kernel_launch(void* const* d_in, const int* in_sizes, int n_in,
                              void* d_out, int out_size)
{
    const float* img  = (const float*)d_in[0];
    const int*   rois = (const int*)d_in[1];
    float*       out  = (float*)d_out;

    // No shared memory used: maximize the L1 carveout.
    cudaFuncSetAttribute(roi_pool_kernel,
                         cudaFuncAttributePreferredSharedMemoryCarveout,
                         cudaSharedmemCarveoutMaxL1);

    const int grid = NROIS * POOL;        // 3584 CTAs, one per (roi, py)
    roi_pool_kernel<<<grid, 128>>>(img, rois, out);
}